// round 7
// baseline (speedup 1.0000x reference)
#include <cuda_runtime.h>
#include <math.h>

#define N 4096
#define NTHREADS 1024
#define NCTA_ROW 64
#define SLICE 64
#define NCHUNK 64
#define CHUNK 64

typedef unsigned long long u64;
typedef unsigned int u32;

__device__ u64   g_keys[2][N];
__device__ float g_rank[2][N];
__device__ int   g_fStart[2][N + 1];
__device__ float g_fS[2][N];
__device__ int   g_nb[2];
__device__ float g_part[2 * NCTA_ROW][3];
__device__ u32   g_cnt[2];
__device__ u32   g_cnt2;
__device__ u32   g_done[2];

// ---- float -> order-preserving uint (ascending), exact inverse ----
__device__ __forceinline__ u32 encodeVal(float v) {
    u32 b = __float_as_uint(v);
    return (b & 0x80000000u) ? ~b : (b | 0x80000000u);
}
__device__ __forceinline__ float decodeVal(u32 e) {
    return (e & 0x80000000u) ? __uint_as_float(e ^ 0x80000000u)
                             : __uint_as_float(~e);
}

// exact integer W(start,cnt) = cnt*N - sum(start..start+cnt-1)
__device__ __forceinline__ float Wf(int s, int c) {
    return (float)(c * N - (((2 * s + c - 1) * c) >> 1));
}

__device__ __forceinline__ float blockReduceSum(float v, float* scratch) {
#pragma unroll
    for (int o = 16; o; o >>= 1) v += __shfl_down_sync(0xffffffffu, v, o);
    int w = threadIdx.x >> 5, l = threadIdx.x & 31;
    __syncthreads();
    if (l == 0) scratch[w] = v;
    __syncthreads();
    if (w == 0) {
        float t = scratch[l];   // exactly 32 warps
#pragma unroll
        for (int o = 16; o; o >>= 1) t += __shfl_down_sync(0xffffffffu, t, o);
        if (l == 0) scratch[0] = t;
    }
    __syncthreads();
    return scratch[0];
}

// SMEM: kArr u64[N]; bStart i[N]; bCnt i[N]; bSum f[N]; fStart i[N+1]; fS f[N];
//       cntArr i[64]; nbPtr; red f[32]; shWho u32[2]
#define SMEM_BYTES (N * 8 + 3 * N * 4 + (N + 1) * 4 + N * 4 + NCHUNK * 4 + 4 + 32 * 4 + 8 + 64)

__global__ __launch_bounds__(NTHREADS, 1)
void fusedKernel(const float* __restrict__ yhat,
                 const float* __restrict__ ytar,
                 float* __restrict__ out) {
    extern __shared__ u64 smemBase[];
    u64*   kArr   = smemBase;                    // N u64
    int*   bStart = (int*)(kArr + N);            // N
    int*   bCnt   = bStart + N;                  // N
    float* bSum   = (float*)(bCnt + N);          // N
    int*   fStart = (int*)(bSum + N);            // N+1
    float* fS     = (float*)(fStart + N + 1);    // N
    int*   cntArr = (int*)(fS + N);              // NCHUNK
    int*   nbPtr  = cntArr + NCHUNK;             // 1
    float* red    = (float*)(nbPtr + 1);         // 32
    u32*   shWho  = (u32*)(red + 32);            // 2
    u32*   sPart  = (u32*)bStart;                // counting reuse (4KB)

    const int tid  = threadIdx.x;
    const int lane = tid & 31;
    const int wrp  = tid >> 5;
    const int row  = blockIdx.x >> 6;
    const int slot = blockIdx.x & (NCTA_ROW - 1);
    const float* src = row ? ytar : yhat;

    // ============ Phase 1: build unique keys, rank by counting ============
    // K_i = (enc(v_i) << 32) | (N-1-i): descending K == descending v, stable.
    {
        float4 v = ((const float4*)src)[tid];
        int i0 = tid * 4;
        kArr[i0 + 0] = ((u64)encodeVal(v.x) << 32) | (u32)(N - 1 - (i0 + 0));
        kArr[i0 + 1] = ((u64)encodeVal(v.y) << 32) | (u32)(N - 1 - (i0 + 1));
        kArr[i0 + 2] = ((u64)encodeVal(v.z) << 32) | (u32)(N - 1 - (i0 + 2));
        kArr[i0 + 3] = ((u64)encodeVal(v.w) << 32) | (u32)(N - 1 - (i0 + 3));
    }
    __syncthreads();

    {
        // lane = target, warp = value segment. All lanes read the SAME address
        // each iteration -> broadcast LDS, 1 wavefront.
        const int seg = wrp & 15;                  // value segment [seg*256, +256)
        const int g   = wrp >> 4;                  // target group (0 or 1)
        const int ii  = slot * SLICE + g * 32 + lane;
        const u64 ki  = kArr[ii];
        const ulonglong2* base = (const ulonglong2*)(kArr + seg * 256);
        u32 c = 0;
#pragma unroll 8
        for (int t = 0; t < 128; t += 2) {
            ulonglong2 p0 = base[t];
            ulonglong2 p1 = base[t + 1];
            c += (u32)(p0.x > ki) + (u32)(p0.y > ki)
               + (u32)(p1.x > ki) + (u32)(p1.y > ki);
        }
        sPart[wrp * 32 + lane] = c;
    }
    __syncthreads();

    if (tid < SLICE) {
        int g = tid >> 5, ln = tid & 31;
        u32 pos = 0;
#pragma unroll
        for (int s = 0; s < 16; ++s)
            pos += sPart[(g * 16 + s) * 32 + ln];
        g_keys[row][pos] = kArr[slot * SLICE + tid];
    }

    // ============ gate 1: last CTA of this row runs serial PAV ============
    __threadfence();
    __syncthreads();
    if (tid == 0) shWho[0] = atomicAdd(&g_cnt[row], 1);
    __syncthreads();

    if (shWho[0] == NCTA_ROW - 1) {
        __threadfence();   // acquire other CTAs' g_keys writes

        // load sorted keys into SMEM
        {
            const u64* gk = g_keys[row];
#pragma unroll
            for (int m = 0; m < 4; m++) {
                int i = tid + m * NTHREADS;
                kArr[i] = gk[i];
            }
        }
        __syncthreads();

        // per-chunk PAV (nonincreasing fit of z_i = s_i - (N-i))
        if (tid < NCHUNK) {
            const int cbase = tid * CHUNK;
            int myCnt = 0;
            float tS  = decodeVal((u32)(kArr[cbase] >> 32));
            int   tC  = 1, tSt = cbase;
            float tNum = tS - (float)(N - cbase);
            for (int i = cbase + 1; i < cbase + CHUNK; ++i) {
                float s  = decodeVal((u32)(kArr[i] >> 32));
                float cS = s;
                int   cC = 1, cSt = i;
                float cNum = s - (float)(N - i);
                while (tNum * (float)cC < cNum * (float)tC) {
                    cS += tS; cC += tC; cSt = tSt;
                    cNum = cS - Wf(cSt, cC);
                    if (myCnt == 0) { tC = 0; break; }
                    myCnt--;
                    tSt = bStart[cbase + myCnt];
                    tS  = bSum[cbase + myCnt];
                    tC  = bCnt[cbase + myCnt];
                    tNum = tS - Wf(tSt, tC);
                }
                if (tC > 0) {
                    bStart[cbase + myCnt] = tSt; bSum[cbase + myCnt] = tS; bCnt[cbase + myCnt] = tC;
                    myCnt++;
                }
                tS = cS; tC = cC; tSt = cSt; tNum = cNum;
            }
            bStart[cbase + myCnt] = tSt; bSum[cbase + myCnt] = tS; bCnt[cbase + myCnt] = tC;
            cntArr[tid] = myCnt + 1;
        }
        __syncthreads();

        // serial merge of chunk block lists (blocks as atoms)
        if (tid == 0) {
            int nb = 0;
            int   tSt = bStart[0], tC = bCnt[0];
            float tS  = bSum[0];
            float tNum = tS - Wf(tSt, tC);
            for (int c = 0; c < NCHUNK; ++c) {
                int m = cntArr[c];
                for (int b = (c == 0) ? 1 : 0; b < m; ++b) {
                    int off = c * CHUNK + b;
                    int   cSt = bStart[off], cC = bCnt[off];
                    float cS  = bSum[off];
                    float cNum = cS - Wf(cSt, cC);
                    while (tNum * (float)cC < cNum * (float)tC) {
                        cS += tS; cC += tC; cSt = tSt;
                        cNum = cS - Wf(cSt, cC);
                        if (nb == 0) { tC = 0; break; }
                        nb--;
                        int pSt = fStart[nb];
                        tS  = fS[nb];
                        tC  = cSt - pSt;
                        tSt = pSt;
                        tNum = tS - Wf(tSt, tC);
                    }
                    if (tC > 0) { fStart[nb] = tSt; fS[nb] = tS; nb++; }
                    tS = cS; tC = cC; tSt = cSt; tNum = cNum;
                }
            }
            fStart[nb] = tSt; fS[nb] = tS; nb++;
            fStart[nb] = N;
            *nbPtr = nb;
        }
        __syncthreads();

        const int nb = *nbPtr;
        // block dual means + publish to global
        for (int b = tid; b < nb; b += NTHREADS) {
            int s0 = fStart[b], cc = fStart[b + 1] - s0;
            float mean = (fS[b] - Wf(s0, cc)) / (float)cc;
            g_fStart[row][b] = s0;
            g_fS[row][b] = mean;
        }
        if (tid == 0) {
            g_fStart[row][nb] = N;
            g_nb[row] = nb;
        }
        __threadfence();
        __syncthreads();
        if (tid == 0) *((volatile u32*)&g_done[row]) = 1;   // release
    }

    // ============ all CTAs: wait for own row's PAV results ============
    if (tid == 0) {
        while (*((volatile u32*)&g_done[row]) == 0) __nanosleep(64);
    }
    __syncthreads();
    __threadfence();   // acquire

    const int nb = g_nb[row];
    for (int b = tid; b <= nb; b += NTHREADS) bStart[b] = g_fStart[row][b];
    for (int b = tid; b < nb;  b += NTHREADS) bSum[b]  = g_fS[row][b];
    __syncthreads();

    // scatter this CTA's 64 sorted positions; accumulate partial moments
    float sR = 0.f, sR2 = 0.f, sB = 0.f;
    if (tid < SLICE) {
        int i = slot * SLICE + tid;            // sorted position
        u64 kk = g_keys[row][i];
        float s = decodeVal((u32)(kk >> 32));
        int  id = N - 1 - (int)(kk & 0xFFFFFFFFu);
        int lo = 0, hi = nb - 1;
        while (lo < hi) {
            int mid = (lo + hi + 1) >> 1;
            if (bStart[mid] <= i) lo = mid; else hi = mid - 1;
        }
        float r = s - bSum[lo] - 2048.5f;      // shift is Spearman-invariant
        g_rank[row][id] = r;
        sR  = r;
        sR2 = r * r;
        if (row == 1) {                        // BCE over index slice (once)
            int ix = slot * SLICE + tid;
            float x  = yhat[ix];
            float yy = ytar[ix];
            sB = fmaxf(x, 0.f) + log1pf(expf(-fabsf(x))) - x * yy;
        }
    }
    sR  = blockReduceSum(sR, red);
    sR2 = blockReduceSum(sR2, red);
    sB  = blockReduceSum(sB, red);
    if (tid == 0) {
        g_part[blockIdx.x][0] = sR;
        g_part[blockIdx.x][1] = sR2;
        g_part[blockIdx.x][2] = sB;
    }

    // ============ gate 2: last of all 128 CTAs finishes ============
    __threadfence();
    __syncthreads();
    if (tid == 0) shWho[1] = atomicAdd(&g_cnt2, 1);
    __syncthreads();
    if (shWho[1] != 2 * NCTA_ROW - 1) return;
    __threadfence();   // acquire all ranks + partials

    {
        float cr = 0.f;
#pragma unroll
        for (int m = 0; m < 4; m++) {
            int i = tid + m * NTHREADS;
            cr += g_rank[0][i] * g_rank[1][i];
        }
        cr = blockReduceSum(cr, red);

        float vP = 0.f, vP2 = 0.f, vT = 0.f, vT2 = 0.f, vB = 0.f;
        if (tid < 2 * NCTA_ROW) {
            float a0 = g_part[tid][0], a1 = g_part[tid][1], a2 = g_part[tid][2];
            if (tid < NCTA_ROW) { vP = a0; vP2 = a1; }
            else                { vT = a0; vT2 = a1; vB = a2; }
        }
        vP  = blockReduceSum(vP,  red);
        vP2 = blockReduceSum(vP2, red);
        vT  = blockReduceSum(vT,  red);
        vT2 = blockReduceSum(vT2, red);
        vB  = blockReduceSum(vB,  red);

        if (tid == 0) {
            float invN = 1.0f / (float)N;
            float mp = vP * invN, mt = vT * invN;
            float varP = vP2 - (float)N * mp * mp;
            float varT = vT2 - (float)N * mt * mt;
            float cov  = cr - (float)N * mp * mt;
            float sp   = cov * rsqrtf(varP * varT);
            out[0] = (1.0f - sp) + vB * invN;
            // reset for next graph replay
            g_cnt[0] = 0; g_cnt[1] = 0; g_cnt2 = 0;
            g_done[0] = 0; g_done[1] = 0;
        }
    }
}

extern "C" void kernel_launch(void* const* d_in, const int* in_sizes, int n_in,
                              void* d_out, int out_size) {
    const float* yhat = (const float*)d_in[0];
    const float* ytar = (const float*)d_in[1];
    float* out = (float*)d_out;
    cudaFuncSetAttribute(fusedKernel,
                         cudaFuncAttributeMaxDynamicSharedMemorySize, SMEM_BYTES);
    fusedKernel<<<2 * NCTA_ROW, NTHREADS, SMEM_BYTES>>>(yhat, ytar, out);
}

// round 8
// speedup vs baseline: 1.2098x; 1.2098x over previous
#include <cuda_runtime.h>
#include <math.h>

#define N 4096
#define NTHREADS 1024
#define NCTA_ROW 64
#define SLICE 64
#define NCHUNK 64
#define CHUNK 64

typedef unsigned long long u64;
typedef unsigned int u32;

__device__ u64   g_keys[2][N];
__device__ float g_rank[2][N];
__device__ float g_sum[2], g_sumsq[2], g_bce;
__device__ u32   g_cnt[2];
__device__ u32   g_cnt2;

// ---- float -> order-preserving uint (ascending), exact inverse ----
__device__ __forceinline__ u32 encodeVal(float v) {
    u32 b = __float_as_uint(v);
    return (b & 0x80000000u) ? ~b : (b | 0x80000000u);
}
__device__ __forceinline__ float decodeVal(u32 e) {
    return (e & 0x80000000u) ? __uint_as_float(e ^ 0x80000000u)
                             : __uint_as_float(~e);
}

__device__ __forceinline__ uint4 packAtom(float S, float W, float C, int st) {
    uint4 a;
    a.x = __float_as_uint(S); a.y = __float_as_uint(W);
    a.z = __float_as_uint(C); a.w = (u32)st;
    return a;
}

__device__ __forceinline__ float blockReduceSum(float v, float* scratch) {
#pragma unroll
    for (int o = 16; o; o >>= 1) v += __shfl_down_sync(0xffffffffu, v, o);
    int w = threadIdx.x >> 5, l = threadIdx.x & 31;
    __syncthreads();
    if (l == 0) scratch[w] = v;
    __syncthreads();
    if (w == 0) {
        float t = scratch[l];   // exactly 32 warps
#pragma unroll
        for (int o = 16; o; o >>= 1) t += __shfl_down_sync(0xffffffffu, t, o);
        if (l == 0) scratch[0] = t;
    }
    __syncthreads();
    return scratch[0];
}

// ---- SMEM byte offsets ----
#define SM_KARR   0                     // u64[4096]   32768
#define SM_STK    32768                 // uint4[4096] 65536  (sPart overlays)
#define SM_DENSE  98304                 // uint4[4096] 65536  (rLoc overlays)
#define SM_FSTART 163840                // int[4097]   16388
#define SM_FMEAN  180228                // float[4096] 16384
#define SM_CNT    196612                // int[64]
#define SM_OFF    196868                // int[64]
#define SM_RED    197124                // float[32]
#define SM_WHO    197252                // u32[2]
#define SM_NB     197260                // int
#define SMEM_BYTES 197280

__global__ __launch_bounds__(NTHREADS, 1)
void fusedKernel(const float* __restrict__ yhat,
                 const float* __restrict__ ytar,
                 float* __restrict__ out) {
    extern __shared__ char sm[];
    u64*   kArr   = (u64*)(sm + SM_KARR);
    uint4* stk    = (uint4*)(sm + SM_STK);
    u32*   sPart  = (u32*)(sm + SM_STK);      // counting-phase overlay
    uint4* dense  = (uint4*)(sm + SM_DENSE);
    float* rLoc   = (float*)(sm + SM_DENSE);  // scatter-phase overlay
    int*   fStart = (int*)(sm + SM_FSTART);
    float* fMean  = (float*)(sm + SM_FMEAN);
    int*   cntArr = (int*)(sm + SM_CNT);
    int*   offArr = (int*)(sm + SM_OFF);
    float* red    = (float*)(sm + SM_RED);
    u32*   shWho  = (u32*)(sm + SM_WHO);
    int*   nbPtr  = (int*)(sm + SM_NB);

    const int tid  = threadIdx.x;
    const int lane = tid & 31;
    const int wrp  = tid >> 5;
    const int row  = blockIdx.x >> 6;
    const int slot = blockIdx.x & (NCTA_ROW - 1);
    const float* src = row ? ytar : yhat;

    // ============ Phase 1: unique keys + rank by counting (128 CTAs) ========
    // K_i = (enc(v_i) << 32) | (N-1-i): descending K == descending v, stable.
    {
        float4 v = ((const float4*)src)[tid];
        int i0 = tid * 4;
        kArr[i0 + 0] = ((u64)encodeVal(v.x) << 32) | (u32)(N - 1 - (i0 + 0));
        kArr[i0 + 1] = ((u64)encodeVal(v.y) << 32) | (u32)(N - 1 - (i0 + 1));
        kArr[i0 + 2] = ((u64)encodeVal(v.z) << 32) | (u32)(N - 1 - (i0 + 2));
        kArr[i0 + 3] = ((u64)encodeVal(v.w) << 32) | (u32)(N - 1 - (i0 + 3));
    }
    __syncthreads();

    {
        // lane = target, warp = value segment; all lanes read the SAME address
        // per iteration -> broadcast LDS, 1 wavefront.
        const int seg = wrp & 15;
        const int g   = wrp >> 4;
        const int ii  = slot * SLICE + g * 32 + lane;
        const u64 ki  = kArr[ii];
        const ulonglong2* base = (const ulonglong2*)(kArr + seg * 256);
        u32 c = 0;
#pragma unroll 8
        for (int t = 0; t < 128; t += 2) {
            ulonglong2 p0 = base[t];
            ulonglong2 p1 = base[t + 1];
            c += (u32)(p0.x > ki) + (u32)(p0.y > ki)
               + (u32)(p1.x > ki) + (u32)(p1.y > ki);
        }
        sPart[wrp * 32 + lane] = c;
    }
    __syncthreads();

    if (tid < SLICE) {
        int g = tid >> 5, ln = tid & 31;
        u32 pos = 0;
#pragma unroll
        for (int s = 0; s < 16; ++s)
            pos += sPart[(g * 16 + s) * 32 + ln];
        g_keys[row][pos] = kArr[slot * SLICE + tid];
    }

    // ============ gate 1: last CTA per row continues; rest exit ============
    __threadfence();
    __syncthreads();
    if (tid == 0) shWho[0] = atomicAdd(&g_cnt[row], 1);
    __syncthreads();
    if (shWho[0] != NCTA_ROW - 1) return;
    __threadfence();   // acquire other CTAs' g_keys writes

    // ============ Phase 2: PAV (1 CTA per row) ============
    {
        const u64* gk = g_keys[row];
#pragma unroll
        for (int m = 0; m < 4; m++) {
            int i = tid + m * NTHREADS;
            kArr[i] = gk[i];
        }
    }
    __syncthreads();

    // per-chunk PAV, all-float block state (exact: |sumW| < 2^24)
    if (tid < NCHUNK) {
        const int base = tid * CHUNK;
        float w  = (float)(N - base);            // w(i) = N - i, running
        float tS = decodeVal((u32)(kArr[base] >> 32));
        float tW = w, tC = 1.f;
        float tNum = tS - tW;
        int   tSt = base, sp = 0;
        for (int i = base + 1; i < base + CHUNK; ++i) {
            w -= 1.f;
            float s = decodeVal((u32)(kArr[i] >> 32));
            float cS = s, cW = w, cC = 1.f, cNum = s - w;
            int   cSt = i;
            while (tNum * cC < cNum * tC) {      // pool
                cS += tS; cW += tW; cC += tC; cSt = tSt;
                cNum = cS - cW;
                if (sp == 0) { tC = 0.f; break; }
                sp--;
                uint4 a = stk[base + sp];
                tS = __uint_as_float(a.x); tW = __uint_as_float(a.y);
                tC = __uint_as_float(a.z); tSt = (int)a.w;
                tNum = tS - tW;
            }
            if (tC > 0.f) { stk[base + sp] = packAtom(tS, tW, tC, tSt); sp++; }
            tS = cS; tW = cW; tC = cC; tSt = cSt; tNum = cNum;
        }
        stk[base + sp] = packAtom(tS, tW, tC, tSt); sp++;
        cntArr[tid] = sp;
    }
    __syncthreads();

    // per-chunk offsets (parallel partial sums; counts are tiny)
    if (tid < NCHUNK) {
        int o = 0;
        for (int j = 0; j < tid; j++) o += cntArr[j];
        offArr[tid] = o;
    }
    __syncthreads();

    // compact atoms to dense
    if (tid < NCHUNK) {
        int o = offArr[tid], c = cntArr[tid];
        for (int b = 0; b < c; b++) dense[o + b] = stk[tid * CHUNK + b];
    }
    __syncthreads();

    const int natoms = offArr[NCHUNK - 1] + cntArr[NCHUNK - 1];

    // serial merge over dense atoms (prefetched); final stack reuses stk
    if (tid == 0) {
        uint4 a0 = dense[0];
        float tS = __uint_as_float(a0.x), tW = __uint_as_float(a0.y);
        float tC = __uint_as_float(a0.z);
        int   tSt = (int)a0.w;
        float tNum = tS - tW;
        int sp = 0;
        uint4 nxt = dense[(natoms > 1) ? 1 : 0];
        for (int t = 1; t < natoms; ++t) {
            uint4 a = nxt;
            nxt = dense[(t + 1 < natoms) ? (t + 1) : t];   // prefetch
            float cS = __uint_as_float(a.x), cW = __uint_as_float(a.y);
            float cC = __uint_as_float(a.z);
            int   cSt = (int)a.w;
            float cNum = cS - cW;
            while (tNum * cC < cNum * tC) {
                cS += tS; cW += tW; cC += tC; cSt = tSt;
                cNum = cS - cW;
                if (sp == 0) { tC = 0.f; break; }
                sp--;
                uint4 p = stk[sp];
                tS = __uint_as_float(p.x); tW = __uint_as_float(p.y);
                tC = __uint_as_float(p.z); tSt = (int)p.w;
                tNum = tS - tW;
            }
            if (tC > 0.f) { stk[sp] = packAtom(tS, tW, tC, tSt); sp++; }
            tS = cS; tW = cW; tC = cC; tSt = cSt; tNum = cNum;
        }
        stk[sp] = packAtom(tS, tW, tC, tSt); sp++;
        *nbPtr = sp;
    }
    __syncthreads();

    const int nb = *nbPtr;
    for (int b = tid; b < nb; b += NTHREADS) {
        uint4 a = stk[b];
        fStart[b] = (int)a.w;
        fMean[b]  = (__uint_as_float(a.x) - __uint_as_float(a.y))
                    / __uint_as_float(a.z);
    }
    if (tid == 0) fStart[nb] = N;
    __syncthreads();

    // ---- scatter + own-row moments (1024 threads) ----
    float sR = 0.f, sR2 = 0.f;
#pragma unroll
    for (int m = 0; m < 4; m++) {
        int i = tid + m * NTHREADS;
        u64 kk = kArr[i];
        float s = decodeVal((u32)(kk >> 32));
        int  id = N - 1 - (int)(kk & 0xFFFFFFFFu);
        int lo = 0, hi = nb - 1;
        while (lo < hi) {
            int mid = (lo + hi + 1) >> 1;
            if (fStart[mid] <= i) lo = mid; else hi = mid - 1;
        }
        float r = s - fMean[lo] - 2048.5f;     // shift is Spearman-invariant
        g_rank[row][id] = r;
        rLoc[id] = r;
        sR  += r;
        sR2 += r * r;
    }
    float S  = blockReduceSum(sR, red);
    float S2 = blockReduceSum(sR2, red);

    float B = 0.f;
    if (row == 1) {
        float4 x4 = ((const float4*)yhat)[tid];
        float4 y4 = ((const float4*)ytar)[tid];
        float sb = 0.f;
        sb += fmaxf(x4.x, 0.f) + log1pf(expf(-fabsf(x4.x))) - x4.x * y4.x;
        sb += fmaxf(x4.y, 0.f) + log1pf(expf(-fabsf(x4.y))) - x4.y * y4.y;
        sb += fmaxf(x4.z, 0.f) + log1pf(expf(-fabsf(x4.z))) - x4.z * y4.z;
        sb += fmaxf(x4.w, 0.f) + log1pf(expf(-fabsf(x4.w))) - x4.w * y4.w;
        B = blockReduceSum(sb, red);
    }
    if (tid == 0) {
        g_sum[row]   = S;
        g_sumsq[row] = S2;
        if (row == 1) g_bce = B;
    }

    // ============ gate 2: second of the two row CTAs finishes ============
    __threadfence();
    __syncthreads();
    if (tid == 0) shWho[1] = atomicAdd(&g_cnt2, 1);
    __syncthreads();
    if (shWho[1] != 1) return;
    __threadfence();   // acquire other row's ranks + partials

    {
        const float* other = g_rank[1 - row];
        float cr = 0.f;
#pragma unroll
        for (int m = 0; m < 4; m++) {
            int i = tid + m * NTHREADS;
            cr += other[i] * rLoc[i];
        }
        cr = blockReduceSum(cr, red);
        if (tid == 0) {
            float invN = 1.0f / (float)N;
            float mp = g_sum[0] * invN, mt = g_sum[1] * invN;
            float varP = g_sumsq[0] - (float)N * mp * mp;
            float varT = g_sumsq[1] - (float)N * mt * mt;
            float cov  = cr - (float)N * mp * mt;
            float sp   = cov * rsqrtf(varP * varT);
            out[0] = (1.0f - sp) + g_bce * invN;
            g_cnt[0] = 0; g_cnt[1] = 0; g_cnt2 = 0;   // reset for graph replay
        }
    }
}

extern "C" void kernel_launch(void* const* d_in, const int* in_sizes, int n_in,
                              void* d_out, int out_size) {
    const float* yhat = (const float*)d_in[0];
    const float* ytar = (const float*)d_in[1];
    float* out = (float*)d_out;
    cudaFuncSetAttribute(fusedKernel,
                         cudaFuncAttributeMaxDynamicSharedMemorySize, SMEM_BYTES);
    fusedKernel<<<2 * NCTA_ROW, NTHREADS, SMEM_BYTES>>>(yhat, ytar, out);
}